// round 16
// baseline (speedup 1.0000x reference)
#include <cuda_runtime.h>
#include <cstdint>
#include <cstddef>

#define BB 128
#define TT 256
#define EMBD 200
#define NU1 400
#define NU2 200

// output layout: out2 | out1 | h2 | h1
#define OUT2_OFF 0
#define OUT1_OFF (BB*TT*NU2)
#define H2_OFF   (OUT1_OFF + BB*TT*NU1)
#define H1_OFF   (H2_OFF + BB*NU2)

__device__ float g_xn [(size_t)BB*TT*EMBD];
__device__ float g_xw1[(size_t)BB*TT*3*NU1];
__device__ unsigned g_flag[32*32];          // one 128B line per producer CTA

// ---- cp.async helpers ----
__device__ __forceinline__ void cp_async16(uint32_t s, const void* g)
{
    asm volatile("cp.async.cg.shared.global [%0], [%1], 16;" :: "r"(s), "l"(g));
}
__device__ __forceinline__ void cp_commit() { asm volatile("cp.async.commit_group;"); }
__device__ __forceinline__ void cp_wait0()  { asm volatile("cp.async.wait_all;"); }
__device__ __forceinline__ void cp_wait1()  { asm volatile("cp.async.wait_group 1;"); }

// packed f32x2 ops (sm_10x)
__device__ __forceinline__ unsigned long long fma2(unsigned long long a, unsigned long long b,
                                                   unsigned long long c)
{
    unsigned long long d;
    asm("fma.rn.f32x2 %0, %1, %2, %3;" : "=l"(d) : "l"(a), "l"(b), "l"(c));
    return d;
}
__device__ __forceinline__ unsigned long long pack2(float lo, float hi)
{
    unsigned long long d;
    asm("mov.b64 %0, {%1, %2};" : "=l"(d) : "f"(lo), "f"(hi));
    return d;
}
__device__ __forceinline__ float2 unpack2(unsigned long long a)
{
    return *reinterpret_cast<float2*>(&a);
}

// flag primitives
__device__ __forceinline__ void st_release(unsigned* p, unsigned v)
{
    asm volatile("st.release.gpu.global.u32 [%0], %1;" :: "l"(p), "r"(v) : "memory");
}
__device__ __forceinline__ unsigned ld_acquire(const unsigned* p)
{
    unsigned v;
    asm volatile("ld.acquire.gpu.global.u32 %0, [%1];" : "=r"(v) : "l"(p) : "memory");
    return v;
}

__global__ void embed_bn(const int* __restrict__ tokens, const float* __restrict__ emb,
                         const float* __restrict__ gamma, const float* __restrict__ beta,
                         const float* __restrict__ mmean, const float* __restrict__ mvar)
{
    int idx = blockIdx.x * blockDim.x + threadIdx.x;
    if (idx >= BB*TT*EMBD) return;
    int d = idx % EMBD;
    int m = idx / EMBD;              // m = t*128 + b
    int b = m & (BB-1), t = m >> 7;
    int tok = tokens[b*TT + t];
    float s = gamma[d] * rsqrtf(mvar[d] + 1e-3f);
    g_xn[idx] = (emb[(size_t)tok*EMBD + d] - mmean[d]) * s + beta[d];
}

__global__ void init_flags()
{
    int i = blockIdx.x * blockDim.x + threadIdx.x;
    if (i < 32*32) g_flag[i] = 0;
}

// ---------------- SGEMM1: 128x128 tile, 8x8/thread, f32x2 (proven) ----------------
__global__ void __launch_bounds__(256, 2)
sgemm128(const float* __restrict__ A, const float* __restrict__ Bw,
         const float* __restrict__ bias, float* __restrict__ C, int N, int K)
{
    constexpr int AP = 132, BP = 132;
    __shared__ float As[2][8][AP];
    __shared__ float Bs[2][8][BP];
    const int tid = threadIdx.x;
    const int col0 = blockIdx.x * 128;
    const int row0 = blockIdx.y * 128;
    const int tx = tid & 15, ty = tid >> 4;

    for (int i = tid; i < 2*8*BP; i += 256) (&Bs[0][0][0])[i] = 0.f;
    __syncthreads();

    const int bkk = tid >> 5, bnq = (tid & 31) * 4;
    const int bgc = col0 + bnq;
    uint32_t bs_s0 = (uint32_t)__cvta_generic_to_shared(&Bs[0][bkk][bnq]);
    uint32_t bs_s1 = (uint32_t)__cvta_generic_to_shared(&Bs[1][bkk][bnq]);

    float4 rA;
    auto loadA = [&](int k0) {
        int m = tid >> 1, kq = (tid & 1) * 4;
        rA = *reinterpret_cast<const float4*>(A + (size_t)(row0 + m)*K + k0 + kq);
    };
    auto stsA = [&](int buf) {
        int m = tid >> 1, kq = (tid & 1) * 4;
        As[buf][kq+0][m] = rA.x; As[buf][kq+1][m] = rA.y;
        As[buf][kq+2][m] = rA.z; As[buf][kq+3][m] = rA.w;
    };
    auto asyncB = [&](int k0, int buf) {
        if (bgc < N)
            cp_async16(buf ? bs_s1 : bs_s0, Bw + (size_t)(k0 + bkk)*N + bgc);
    };

    loadA(0);
    asyncB(0, 0);
    cp_commit();

    unsigned long long acc[4][8] = {};
    const int NC = K / 8;
    for (int c = 0; c < NC; c++) {
        int buf = c & 1;
        cp_wait0();
        stsA(buf);
        __syncthreads();
        if (c + 1 < NC) {
            loadA((c+1)*8);
            asyncB((c+1)*8, buf ^ 1);
            cp_commit();
        }
#pragma unroll
        for (int kk = 0; kk < 8; kk++) {
            ulonglong2 a01 = *reinterpret_cast<const ulonglong2*>(&As[buf][kk][ty*8]);
            ulonglong2 a23 = *reinterpret_cast<const ulonglong2*>(&As[buf][kk][ty*8 + 4]);
            float4 b0 = *reinterpret_cast<const float4*>(&Bs[buf][kk][tx*4]);
            float4 b1 = *reinterpret_cast<const float4*>(&Bs[buf][kk][64 + tx*4]);
            unsigned long long ap[4] = {a01.x, a01.y, a23.x, a23.y};
            unsigned long long bd[8];
            bd[0] = pack2(b0.x, b0.x); bd[1] = pack2(b0.y, b0.y);
            bd[2] = pack2(b0.z, b0.z); bd[3] = pack2(b0.w, b0.w);
            bd[4] = pack2(b1.x, b1.x); bd[5] = pack2(b1.y, b1.y);
            bd[6] = pack2(b1.z, b1.z); bd[7] = pack2(b1.w, b1.w);
#pragma unroll
            for (int r = 0; r < 4; r++)
#pragma unroll
                for (int cc = 0; cc < 8; cc++)
                    acc[r][cc] = fma2(ap[r], bd[cc], acc[r][cc]);
        }
        __syncthreads();
    }

#pragma unroll
    for (int r = 0; r < 4; r++) {
        size_t gr = row0 + ty*8 + r*2;
#pragma unroll
        for (int cc = 0; cc < 8; cc++) {
            int gc = col0 + (cc < 4 ? tx*4 + cc : 64 + tx*4 + (cc - 4));
            if (gc < N) {
                float2 v = unpack2(acc[r][cc]);
                float bv = bias[gc];
                C[gr*N + gc]       = v.x + bv;
                C[(gr + 1)*N + gc] = v.y + bv;
            }
        }
    }
}

// ================= zero-sync persistent GRU: 32 L1 CTAs + 32 L2 CTAs =================
// Each CTA owns 4 batches and ALL units of its layer; weights streamed from L2 each step.
// L1 free-runs (no inter-CTA sync). L2 CTA i waits only on flag[i] (point-to-point).
#define NTHR 600
#define L1C 32
// L1 smem: chunks 3*12000 + xw 2*4800 + hp 1600 + mask 32 = 47232 floats
#define FUSED_SMEM (47232*4)

__global__ void __launch_bounds__(NTHR, 1)
fused_gru(const float* __restrict__ xw1, const float* __restrict__ Ur1,
          const float* __restrict__ br1, const float* __restrict__ W2,
          const float* __restrict__ Ur2, const float* __restrict__ b2full,
          const int* __restrict__ tokens, float* __restrict__ dout)
{
    extern __shared__ float sm[];
    const int tid = threadIdx.x;
    float* out2 = dout + OUT2_OFF;
    float* out1 = dout + OUT1_OFF;
    float* h2o  = dout + H2_OFF;
    float* h1o  = dout + H1_OFF;

    if (blockIdx.x < L1C) {
        // ---------------- L1 role: 4 batches x 400 units, U1 streamed ----------------
        constexpr int CK = 10, NCH = 40, CW = 3*NU1;   // chunk [10][1200]
        float*      sChunk = sm;                        // [3][12000]
        float*      sXw    = sChunk + 3*CK*CW;          // [2][4800]
        ulonglong2* hp     = (ulonglong2*)(sXw + 2*4*CW);  // [400]
        unsigned*   sMask  = (unsigned*)(hp + NU1);     // [4][8]

        const int c  = blockIdx.x;
        const int b0 = c*4;
        const int u  = tid;                             // unit (tid < 400)

        for (int i = tid; i < 4*8; i += NTHR) {
            int bb = i >> 3, wd = i & 7;
            unsigned m = 0;
            for (int j = 0; j < 32; j++)
                m |= (tokens[(b0 + bb)*TT + wd*32 + j] != 0 ? 1u : 0u) << j;
            sMask[i] = m;
        }
        if (u < NU1) { ulonglong2 z; z.x = 0; z.y = 0; hp[u] = z; }

        float bz = 0, brr = 0, bh = 0;
        if (u < NU1) { bz = br1[u]; brr = br1[NU1 + u]; bh = br1[2*NU1 + u]; }
        float h0 = 0.f, h1 = 0.f, h2v = 0.f, h3 = 0.f;

        const uint32_t sC_s  = (uint32_t)__cvta_generic_to_shared(sChunk);
        const uint32_t sXw_s = (uint32_t)__cvta_generic_to_shared(sXw);

        // prologue: chunks 0,1 into buf 0,1; xw(0) with chunk 1's group
        for (int i = tid; i < CK*CW/4; i += NTHR)
            cp_async16(sC_s + (uint32_t)i*16, Ur1 + (size_t)i*4);
        cp_commit();
        for (int i = tid; i < CK*CW/4; i += NTHR)
            cp_async16(sC_s + (uint32_t)(CK*CW + i*4)*4, Ur1 + (size_t)CK*CW + i*4);
        for (int i = tid; i < 4*CW/4; i += NTHR)
            cp_async16(sXw_s + (uint32_t)i*16, xw1 + ((size_t)0*BB + b0)*CW + (size_t)i*4);
        cp_commit();
        __syncthreads();

        int cur = 0;   // buffer holding chunk being computed
        for (int t = 0; t < TT; t++) {
            unsigned long long az01 = 0, az23 = 0, ar01 = 0, ar23 = 0, ah01 = 0, ah23 = 0;
            for (int ch = 0; ch < NCH; ch++) {
                cp_wait1();
                __syncthreads();
                // issue chunk ch+2 (wraps to next step's chunk — same weights)
                {
                    int nc = ch + 2; if (nc >= NCH) nc -= NCH;
                    int nbuf = cur + 2; if (nbuf >= 3) nbuf -= 3;
                    uint32_t dst = sC_s + (uint32_t)(nbuf*CK*CW)*4;
                    const float* src = Ur1 + (size_t)nc*CK*CW;
                    for (int i = tid; i < CK*CW/4; i += NTHR)
                        cp_async16(dst + (uint32_t)i*16, src + (size_t)i*4);
                    if (ch == 0) {   // fold xw(t+1) prefetch into this group
                        int tn = (t + 1 < TT) ? t + 1 : TT - 1;
                        uint32_t xd = sXw_s + (uint32_t)(((t+1) & 1)*4*CW)*4;
                        const float* xs = xw1 + ((size_t)tn*BB + b0)*CW;
                        for (int i = tid; i < 4*CW/4; i += NTHR)
                            cp_async16(xd + (uint32_t)i*16, xs + (size_t)i*4);
                    }
                    cp_commit();
                }
                if (u < NU1) {
                    const float* cb = sChunk + cur*CK*CW;
#pragma unroll
                    for (int kk = 0; kk < CK; kk++) {
                        ulonglong2 hv = hp[ch*CK + kk];
                        float wz = cb[kk*CW + u];
                        float wr = cb[kk*CW + NU1 + u];
                        float wh = cb[kk*CW + 2*NU1 + u];
                        unsigned long long wz2 = pack2(wz, wz);
                        unsigned long long wr2 = pack2(wr, wr);
                        unsigned long long wh2 = pack2(wh, wh);
                        az01 = fma2(hv.x, wz2, az01); az23 = fma2(hv.y, wz2, az23);
                        ar01 = fma2(hv.x, wr2, ar01); ar23 = fma2(hv.y, wr2, ar23);
                        ah01 = fma2(hv.x, wh2, ah01); ah23 = fma2(hv.y, wh2, ah23);
                    }
                }
                cur = cur + 1; if (cur >= 3) cur -= 3;
            }
            if (u < NU1) {
                float2 vz01 = unpack2(az01), vz23 = unpack2(az23);
                float2 vr01 = unpack2(ar01), vr23 = unpack2(ar23);
                float2 vh01 = unpack2(ah01), vh23 = unpack2(ah23);
                float vz[4] = {vz01.x, vz01.y, vz23.x, vz23.y};
                float vr[4] = {vr01.x, vr01.y, vr23.x, vr23.y};
                float vh[4] = {vh01.x, vh01.y, vh23.x, vh23.y};
                float hcur[4] = {h0, h1, h2v, h3};
                const float* xwb = sXw + (t & 1)*4*CW;
#pragma unroll
                for (int b = 0; b < 4; b++) {
                    float xz = xwb[b*CW + u];
                    float xr = xwb[b*CW + NU1 + u];
                    float xh = xwb[b*CW + 2*NU1 + u];
                    float z  = 1.f / (1.f + __expf(-(xz + vz[b] + bz)));
                    float r  = 1.f / (1.f + __expf(-(xr + vr[b] + brr)));
                    float hh = tanhf(xh + r * (vh[b] + bh));
                    float hnew = z*hcur[b] + (1.f - z)*hh;
                    int mk = (sMask[b*8 + (t >> 5)] >> (t & 31)) & 1;
                    hcur[b] = mk ? hnew : hcur[b];
                    out1[((size_t)(b0 + b)*TT + t)*NU1 + u] = hcur[b];
                    if (t == TT - 1) h1o[(size_t)(b0 + b)*NU1 + u] = hcur[b];
                }
                h0 = hcur[0]; h1 = hcur[1]; h2v = hcur[2]; h3 = hcur[3];
                ulonglong2 np; np.x = pack2(h0, h1); np.y = pack2(h2v, h3);
                hp[u] = np;
            }
            __syncthreads();
            if (tid == 0) st_release(g_flag + c*32, (unsigned)(t + 1));
        }
    } else {
        // ---------------- L2 role: 4 batches x 200 units, W2+U2 streamed ----------------
        constexpr int CK = 10, CW2 = 3*NU2;             // 600
        constexpr int NCW = 40, NCU = 20, NCT = 60;     // W2 chunks, U2 chunks
        float*      sChunk = sm;                        // [3][6000]
        ulonglong2* o1p    = (ulonglong2*)(sChunk + 3*CK*CW2);   // [400]
        ulonglong2* h2p    = o1p + NU1;                 // [200]
        float*      sAcc   = (float*)(h2p + NU2);       // [600][8]
        unsigned*   sMask  = (unsigned*)(sAcc + 600*8); // [4][8]

        const int ci = blockIdx.x - L1C;
        const int b0 = ci*4;
        const int col = tid;                            // < 600

        for (int i = tid; i < 4*8; i += NTHR) {
            int bb = i >> 3, wd = i & 7;
            unsigned m = 0;
            for (int j = 0; j < 32; j++)
                m |= (tokens[(b0 + bb)*TT + wd*32 + j] != 0 ? 1u : 0u) << j;
            sMask[i] = m;
        }
        if (tid < NU2) { ulonglong2 z; z.x = 0; z.y = 0; h2p[tid] = z; }

        // biases (thread tid<200 = unit): 3 proj + 3 rec
        float biz = 0, bir = 0, bih = 0, brz = 0, brr2 = 0, brh = 0;
        if (tid < NU2) {
            biz = b2full[tid];            bir = b2full[NU2 + tid];      bih = b2full[2*NU2 + tid];
            brz = b2full[CW2 + tid];      brr2 = b2full[CW2 + NU2 + tid]; brh = b2full[CW2 + 2*NU2 + tid];
        }
        float h20 = 0.f, h21 = 0.f, h22 = 0.f, h23 = 0.f;   // h2 for 4 batches (tid<200)

        auto chunk_src = [&](int q) -> const float* {
            return (q < NCW) ? (W2 + (size_t)q*CK*CW2) : (Ur2 + (size_t)(q - NCW)*CK*CW2);
        };
        const uint32_t sC_s = (uint32_t)__cvta_generic_to_shared(sChunk);

        // prologue: chunks 0,1
        for (int i = tid; i < CK*CW2/4; i += NTHR)
            cp_async16(sC_s + (uint32_t)i*16, chunk_src(0) + (size_t)i*4);
        cp_commit();
        for (int i = tid; i < CK*CW2/4; i += NTHR)
            cp_async16(sC_s + (uint32_t)(CK*CW2 + i*4)*4, chunk_src(1) + (size_t)i*4);
        cp_commit();
        __syncthreads();

        int cur = 0;
        for (int t = 0; t < TT; t++) {
            // wait for producer, then stage+pack o1(t)
            if (tid == 0) {
                while (ld_acquire(g_flag + ci*32) < (unsigned)(t + 1)) { }
            }
            __syncthreads();
            if (tid < NU1) {
                int k = tid;
                float v0 = __ldcg(out1 + ((size_t)(b0 + 0)*TT + t)*NU1 + k);
                float v1 = __ldcg(out1 + ((size_t)(b0 + 1)*TT + t)*NU1 + k);
                float v2 = __ldcg(out1 + ((size_t)(b0 + 2)*TT + t)*NU1 + k);
                float v3 = __ldcg(out1 + ((size_t)(b0 + 3)*TT + t)*NU1 + k);
                ulonglong2 pv; pv.x = pack2(v0, v1); pv.y = pack2(v2, v3);
                o1p[k] = pv;
            }
            __syncthreads();

            unsigned long long aP01 = 0, aP23 = 0, aR01 = 0, aR23 = 0;
            for (int q = 0; q < NCT; q++) {
                cp_wait1();
                __syncthreads();
                {
                    int nq = q + 2; if (nq >= NCT) nq -= NCT;
                    int nbuf = cur + 2; if (nbuf >= 3) nbuf -= 3;
                    uint32_t dst = sC_s + (uint32_t)(nbuf*CK*CW2)*4;
                    const float* src = chunk_src(nq);
                    for (int i = tid; i < CK*CW2/4; i += NTHR)
                        cp_async16(dst + (uint32_t)i*16, src + (size_t)i*4);
                    cp_commit();
                }
                const float* cb = sChunk + cur*CK*CW2;
                if (q < NCW) {          // projection over out1(t), K=400
#pragma unroll
                    for (int kk = 0; kk < CK; kk++) {
                        ulonglong2 ov = o1p[q*CK + kk];
                        float wv = cb[kk*CW2 + col];
                        unsigned long long wd = pack2(wv, wv);
                        aP01 = fma2(ov.x, wd, aP01);
                        aP23 = fma2(ov.y, wd, aP23);
                    }
                } else {                // recurrence over h2(t), K=200
#pragma unroll
                    for (int kk = 0; kk < CK; kk++) {
                        ulonglong2 hv = h2p[(q - NCW)*CK + kk];
                        float wv = cb[kk*CW2 + col];
                        unsigned long long wd = pack2(wv, wv);
                        aR01 = fma2(hv.x, wd, aR01);
                        aR23 = fma2(hv.y, wd, aR23);
                    }
                }
                cur = cur + 1; if (cur >= 3) cur -= 3;
            }
            // stage accs: sAcc[col][0..3]=proj b0..3, [4..7]=rec
            {
                float2 p01 = unpack2(aP01), p23 = unpack2(aP23);
                float2 r01 = unpack2(aR01), r23 = unpack2(aR23);
                float* s = sAcc + col*8;
                s[0] = p01.x; s[1] = p01.y; s[2] = p23.x; s[3] = p23.y;
                s[4] = r01.x; s[5] = r01.y; s[6] = r23.x; s[7] = r23.y;
            }
            __syncthreads();
            if (tid < NU2) {
                int uu = tid;
                float hcur[4] = {h20, h21, h22, h23};
#pragma unroll
                for (int b = 0; b < 4; b++) {
                    float Pz = sAcc[(0*NU2 + uu)*8 + b] + biz;
                    float Pr = sAcc[(1*NU2 + uu)*8 + b] + bir;
                    float Ph = sAcc[(2*NU2 + uu)*8 + b] + bih;
                    float Rz = sAcc[(0*NU2 + uu)*8 + 4 + b] + brz;
                    float Rr = sAcc[(1*NU2 + uu)*8 + 4 + b] + brr2;
                    float Rh = sAcc[(2*NU2 + uu)*8 + 4 + b] + brh;
                    float z  = 1.f / (1.f + __expf(-(Pz + Rz)));
                    float r  = 1.f / (1.f + __expf(-(Pr + Rr)));
                    float hh = tanhf(Ph + r * Rh);
                    float hnew = z*hcur[b] + (1.f - z)*hh;
                    int mk = (sMask[b*8 + (t >> 5)] >> (t & 31)) & 1;
                    hcur[b] = mk ? hnew : hcur[b];
                    out2[((size_t)(b0 + b)*TT + t)*NU2 + uu] = hcur[b];
                    if (t == TT - 1) h2o[(size_t)(b0 + b)*NU2 + uu] = hcur[b];
                }
                h20 = hcur[0]; h21 = hcur[1]; h22 = hcur[2]; h23 = hcur[3];
                ulonglong2 np; np.x = pack2(h20, h21); np.y = pack2(h22, h23);
                h2p[uu] = np;
            }
            __syncthreads();
        }
    }
}

extern "C" void kernel_launch(void* const* d_in, const int* in_sizes, int n_in,
                              void* d_out, int out_size)
{
    const int*   tokens = (const int*)  d_in[0];
    const float* emb    = (const float*)d_in[1];
    const float* gamma  = (const float*)d_in[2];
    const float* beta   = (const float*)d_in[3];
    const float* mmean  = (const float*)d_in[4];
    const float* mvar   = (const float*)d_in[5];
    const float* W1     = (const float*)d_in[6];
    const float* Ur1    = (const float*)d_in[7];
    const float* b1     = (const float*)d_in[8];
    const float* W2     = (const float*)d_in[9];
    const float* Ur2    = (const float*)d_in[10];
    const float* b2     = (const float*)d_in[11];

    void *p_xn, *p_xw1;
    cudaGetSymbolAddress(&p_xn,  g_xn);
    cudaGetSymbolAddress(&p_xw1, g_xw1);
    float* xn  = (float*)p_xn;
    float* xw1 = (float*)p_xw1;

    cudaFuncSetAttribute(fused_gru, cudaFuncAttributeMaxDynamicSharedMemorySize, FUSED_SMEM);

    embed_bn<<<(BB*TT*EMBD + 255)/256, 256>>>(tokens, emb, gamma, beta, mmean, mvar);
    init_flags<<<4, 256>>>();

    // xw1 = xn @ W1 + b1[0]
    sgemm128<<<dim3((3*NU1 + 127)/128, (BB*TT)/128), 256>>>(xn, W1, b1, xw1, 3*NU1, EMBD);

    // zero-sync persistent GRU (both layers)
    fused_gru<<<64, NTHR, FUSED_SMEM>>>(xw1, Ur1, b1 + 3*NU1, W2, Ur2, b2,
                                        tokens, (float*)d_out);
}

// round 17
// speedup vs baseline: 2.0149x; 2.0149x over previous
#include <cuda_runtime.h>
#include <cstdint>
#include <cstddef>

#define BB 128
#define TT 256
#define EMBD 200
#define NU1 400
#define NU2 200
#define NU2P 204            // padded h2 row (floats)

// output layout: out2 | out1 | h2 | h1
#define OUT2_OFF 0
#define OUT1_OFF (BB*TT*NU2)
#define H2_OFF   (OUT1_OFF + BB*TT*NU1)
#define H1_OFF   (H2_OFF + BB*NU2)

__device__ float g_xn [(size_t)BB*TT*EMBD];
__device__ float g_xw1[(size_t)BB*TT*3*NU1];
__device__ float g_o1g[(size_t)TT*4*NU1*32];   // out1 [t][grp32][u][32b]
__device__ float g_o2t[(size_t)BB*TT*NU2];     // out2 [t][u][b]
__device__ float g_h1 [2*BB*NU1];
__device__ float g_h2 [2*BB*NU2P];             // padded rows, bulk-copyable
__device__ unsigned g_cnt1[4*32], g_gen1[4*32], g_gen1c[4*32], g_cnt2[4*32], g_gen2[4*32];

// ---- cp.async helpers ----
__device__ __forceinline__ void cp_async16(uint32_t s, const void* g)
{
    asm volatile("cp.async.cg.shared.global [%0], [%1], 16;" :: "r"(s), "l"(g));
}
__device__ __forceinline__ void cp_commit() { asm volatile("cp.async.commit_group;"); }
__device__ __forceinline__ void cp_wait0()  { asm volatile("cp.async.wait_all;"); }

// ---- mbarrier + bulk ----
__device__ __forceinline__ void mbar_init(uint32_t mbar)
{
    asm volatile("mbarrier.init.shared.b64 [%0], 1;" :: "r"(mbar) : "memory");
}
__device__ __forceinline__ void mbar_expect_tx(uint32_t mbar, uint32_t bytes)
{
    asm volatile("mbarrier.arrive.expect_tx.shared.b64 _, [%0], %1;"
                 :: "r"(mbar), "r"(bytes) : "memory");
}
__device__ __forceinline__ void mbar_wait(uint32_t mbar, uint32_t parity)
{
    uint32_t done;
    asm volatile(
        "{\n\t.reg .pred p;\n\t"
        "mbarrier.try_wait.parity.acquire.cta.shared::cta.b64 p, [%1], %2;\n\t"
        "selp.b32 %0, 1, 0, p;\n\t}"
        : "=r"(done) : "r"(mbar), "r"(parity) : "memory");
    if (!done) {
        asm volatile(
            "{\n\t.reg .pred P1;\n\t"
            "WAIT_LOOP_%=:\n\t"
            "mbarrier.try_wait.parity.acquire.cta.shared::cta.b64 P1, [%0], %1, 0x989680;\n\t"
            "@P1 bra.uni WAIT_DONE_%=;\n\t"
            "bra.uni WAIT_LOOP_%=;\n\t"
            "WAIT_DONE_%=:\n\t}"
            :: "r"(mbar), "r"(parity) : "memory");
    }
}
__device__ __forceinline__ void bulk_g2s(uint32_t dst, const void* src, uint32_t bytes,
                                         uint32_t mbar)
{
    asm volatile("cp.async.bulk.shared::cluster.global.mbarrier::complete_tx::bytes "
                 "[%0], [%1], %2, [%3];"
                 :: "r"(dst), "l"(src), "r"(bytes), "r"(mbar) : "memory");
}

// packed f32x2 ops (sm_10x)
__device__ __forceinline__ unsigned long long fma2(unsigned long long a, unsigned long long b,
                                                   unsigned long long c)
{
    unsigned long long d;
    asm("fma.rn.f32x2 %0, %1, %2, %3;" : "=l"(d) : "l"(a), "l"(b), "l"(c));
    return d;
}
__device__ __forceinline__ unsigned long long pack2(float lo, float hi)
{
    unsigned long long d;
    asm("mov.b64 %0, {%1, %2};" : "=l"(d) : "f"(lo), "f"(hi));
    return d;
}
__device__ __forceinline__ float hsum2(unsigned long long a)
{
    float2 f = *reinterpret_cast<float2*>(&a);
    return f.x + f.y;
}
__device__ __forceinline__ float2 unpack2(unsigned long long a)
{
    return *reinterpret_cast<float2*>(&a);
}

// barrier primitives
__device__ __forceinline__ unsigned atom_arrive(unsigned* p)
{
    unsigned arr;
    asm volatile("atom.acq_rel.gpu.global.add.u32 %0, [%1], 1;"
                 : "=r"(arr) : "l"(p) : "memory");
    return arr;
}
__device__ __forceinline__ void st_release(unsigned* p, unsigned v)
{
    asm volatile("st.release.gpu.global.u32 [%0], %1;" :: "l"(p), "r"(v) : "memory");
}
__device__ __forceinline__ void st_relaxed(unsigned* p, unsigned v)
{
    asm volatile("st.relaxed.gpu.global.u32 [%0], %1;" :: "l"(p), "r"(v) : "memory");
}
__device__ __forceinline__ unsigned ld_acquire(const unsigned* p)
{
    unsigned v;
    asm volatile("ld.acquire.gpu.global.u32 %0, [%1];" : "=r"(v) : "l"(p) : "memory");
    return v;
}

__global__ void embed_bn(const int* __restrict__ tokens, const float* __restrict__ emb,
                         const float* __restrict__ gamma, const float* __restrict__ beta,
                         const float* __restrict__ mmean, const float* __restrict__ mvar)
{
    int idx = blockIdx.x * blockDim.x + threadIdx.x;
    if (idx >= BB*TT*EMBD) return;
    int d = idx % EMBD;
    int m = idx / EMBD;              // m = t*128 + b
    int b = m & (BB-1), t = m >> 7;
    int tok = tokens[b*TT + t];
    float s = gamma[d] * rsqrtf(mvar[d] + 1e-3f);
    g_xn[idx] = (emb[(size_t)tok*EMBD + d] - mmean[d]) * s + beta[d];
}

__global__ void init_state()
{
    int i = blockIdx.x * blockDim.x + threadIdx.x;
    if (i < 2*BB*NU1) g_h1[i] = 0.f;
    if (i < 2*BB*NU2P) g_h2[i] = 0.f;
    if (i < 4*32) {
        g_cnt1[i] = 0; g_gen1[i] = 0; g_gen1c[i] = 0; g_cnt2[i] = 0; g_gen2[i] = 0;
    }
}

__global__ void copy_h(const float* __restrict__ src, float* __restrict__ dst, int n)
{
    int i = blockIdx.x * blockDim.x + threadIdx.x;
    if (i < n) dst[i] = src[i];
}
__global__ void copy_h_strided(const float* __restrict__ src, float* __restrict__ dst,
                               int U, int KP)
{
    int i = blockIdx.x * blockDim.x + threadIdx.x;
    if (i < BB*U) dst[i] = src[(i/U)*KP + (i % U)];
}

// o1g [t][grp][u][32] -> out1 [b][t][u];  grid (TT, 25, 4), block (32,8)
__global__ void transpose_o1(const float* __restrict__ src, float* __restrict__ dst)
{
    __shared__ float s[16][33];
    int t = blockIdx.x, u0 = blockIdx.y*16, g = blockIdx.z;
    int xi = threadIdx.x, yj = threadIdx.y;
    for (int r = yj; r < 16; r += 8)
        s[r][xi] = src[(((size_t)t*4 + g)*NU1 + u0 + r)*32 + xi];
    __syncthreads();
    for (int r = yj; r < 32; r += 8)
        if (xi < 16)
            dst[((size_t)(g*32 + r)*TT + t)*NU1 + u0 + xi] = s[xi][r];
}

// o2t [t][u][b] -> out2 [b][t][u]
__global__ void transpose_tub(const float* __restrict__ src, float* __restrict__ dst, int U)
{
    __shared__ float s[32][33];
    int t = blockIdx.x, u0 = blockIdx.y*32, b0 = blockIdx.z*32;
    int xi = threadIdx.x, yj = threadIdx.y;
    for (int i = yj; i < 32; i += 8) {
        int u = u0 + i;
        if (u < U) s[i][xi] = src[((size_t)t*U + u)*BB + b0 + xi];
    }
    __syncthreads();
    for (int i = yj; i < 32; i += 8) {
        int u = u0 + xi;
        if (u < U) dst[((size_t)(b0 + i)*TT + t)*U + u] = s[xi][i];
    }
}

// ---------------- SGEMM1: 128x128 tile, 8x8/thread, f32x2 ----------------
__global__ void __launch_bounds__(256, 2)
sgemm128(const float* __restrict__ A, const float* __restrict__ Bw,
         const float* __restrict__ bias, float* __restrict__ C, int N, int K)
{
    constexpr int AP = 132, BP = 132;
    __shared__ float As[2][8][AP];
    __shared__ float Bs[2][8][BP];
    const int tid = threadIdx.x;
    const int col0 = blockIdx.x * 128;
    const int row0 = blockIdx.y * 128;
    const int tx = tid & 15, ty = tid >> 4;

    for (int i = tid; i < 2*8*BP; i += 256) (&Bs[0][0][0])[i] = 0.f;
    __syncthreads();

    const int bkk = tid >> 5, bnq = (tid & 31) * 4;
    const int bgc = col0 + bnq;
    uint32_t bs_s0 = (uint32_t)__cvta_generic_to_shared(&Bs[0][bkk][bnq]);
    uint32_t bs_s1 = (uint32_t)__cvta_generic_to_shared(&Bs[1][bkk][bnq]);

    float4 rA;
    auto loadA = [&](int k0) {
        int m = tid >> 1, kq = (tid & 1) * 4;
        rA = *reinterpret_cast<const float4*>(A + (size_t)(row0 + m)*K + k0 + kq);
    };
    auto stsA = [&](int buf) {
        int m = tid >> 1, kq = (tid & 1) * 4;
        As[buf][kq+0][m] = rA.x; As[buf][kq+1][m] = rA.y;
        As[buf][kq+2][m] = rA.z; As[buf][kq+3][m] = rA.w;
    };
    auto asyncB = [&](int k0, int buf) {
        if (bgc < N)
            cp_async16(buf ? bs_s1 : bs_s0, Bw + (size_t)(k0 + bkk)*N + bgc);
    };

    loadA(0);
    asyncB(0, 0);
    cp_commit();

    unsigned long long acc[4][8] = {};
    const int NC = K / 8;
    for (int c = 0; c < NC; c++) {
        int buf = c & 1;
        cp_wait0();
        stsA(buf);
        __syncthreads();
        if (c + 1 < NC) {
            loadA((c+1)*8);
            asyncB((c+1)*8, buf ^ 1);
            cp_commit();
        }
#pragma unroll
        for (int kk = 0; kk < 8; kk++) {
            ulonglong2 a01 = *reinterpret_cast<const ulonglong2*>(&As[buf][kk][ty*8]);
            ulonglong2 a23 = *reinterpret_cast<const ulonglong2*>(&As[buf][kk][ty*8 + 4]);
            float4 b0 = *reinterpret_cast<const float4*>(&Bs[buf][kk][tx*4]);
            float4 b1 = *reinterpret_cast<const float4*>(&Bs[buf][kk][64 + tx*4]);
            unsigned long long ap[4] = {a01.x, a01.y, a23.x, a23.y};
            unsigned long long bd[8];
            bd[0] = pack2(b0.x, b0.x); bd[1] = pack2(b0.y, b0.y);
            bd[2] = pack2(b0.z, b0.z); bd[3] = pack2(b0.w, b0.w);
            bd[4] = pack2(b1.x, b1.x); bd[5] = pack2(b1.y, b1.y);
            bd[6] = pack2(b1.z, b1.z); bd[7] = pack2(b1.w, b1.w);
#pragma unroll
            for (int r = 0; r < 4; r++)
#pragma unroll
                for (int cc = 0; cc < 8; cc++)
                    acc[r][cc] = fma2(ap[r], bd[cc], acc[r][cc]);
        }
        __syncthreads();
    }

#pragma unroll
    for (int r = 0; r < 4; r++) {
        size_t gr = row0 + ty*8 + r*2;
#pragma unroll
        for (int cc = 0; cc < 8; cc++) {
            int gc = col0 + (cc < 4 ? tx*4 + cc : 64 + tx*4 + (cc - 4));
            if (gc < N) {
                float2 v = unpack2(acc[r][cc]);
                float bv = bias[gc];
                C[gr*N + gc]       = v.x + bv;
                C[(gr + 1)*N + gc] = v.y + bv;
            }
        }
    }
}

// ================= fused persistent kernel: L1 (100 CTAs) + L2 (40 CTAs) =================
#define NTHR 320
#define L1_CTAS 100
// L2 role smem: 223232 B data + 1024 B mask + 2 mbarriers -> fits in 224288
#define FUSED_SMEM 224288

__global__ void __launch_bounds__(NTHR, 1)
fused_gru(const float* __restrict__ xw1, const float* __restrict__ Ur1,
          const float* __restrict__ br1, const float* __restrict__ W2,
          const float* __restrict__ Ur2, const float* __restrict__ b2full,
          const int* __restrict__ tokens,
          float* __restrict__ o1g, float* __restrict__ o2t,
          float* __restrict__ h1p, float* __restrict__ h2p)
{
    extern __shared__ float sm[];
    const int tid  = threadIdx.x;
    const int w    = tid >> 5;
    const int lane = tid & 31;

    if (blockIdx.x < L1_CTAS) {
        // ---------------- L1 role (R14-verbatim) ----------------
        constexpr int UT = 16, KP = NU1 + 4, XS = 3*UT;
        float*    sU    = sm;
        float*    sH    = sU + 3*UT*KP;
        float*    sX    = sH + 32*KP;
        unsigned* sMask = (unsigned*)(sX + 2*32*XS);

        const int u0  = (blockIdx.x % 25) * UT;
        const int grp = blockIdx.x / 25;
        const int b0  = grp * 32;
        const int b   = b0 + lane;
        const int uu0 = u0 + w*2;

        for (int i = tid; i < 3*UT*NU1; i += NTHR) {
            int k = i / (3*UT), c = i % (3*UT);
            int g = c / UT, lu = c % UT;
            sU[(lu*3 + g)*KP + k] = Ur1[(size_t)k*(3*NU1) + g*NU1 + u0 + lu];
        }
        for (int i = tid; i < 32*8; i += NTHR) {
            int bb = i >> 3, wd = i & 7;
            unsigned m = 0;
            for (int j = 0; j < 32; j++)
                m |= (tokens[(b0 + bb)*TT + wd*32 + j] != 0 ? 1u : 0u) << j;
            sMask[bb*8 + wd] = m;
        }
        const uint32_t sX_s = (uint32_t)__cvta_generic_to_shared(sX);
        const uint32_t sH_s = (uint32_t)__cvta_generic_to_shared(sH);
        for (int i = tid; i < 32*(XS/4); i += NTHR) {
            int bb = i / (XS/4), q = i % (XS/4);
            int g = q / (UT/4), l4 = q % (UT/4);
            cp_async16(sX_s + (uint32_t)(bb*XS + g*UT + l4*4)*4,
                       xw1 + (size_t)(b0 + bb)*(3*NU1) + (size_t)g*NU1 + u0 + l4*4);
        }
        cp_commit();

        float bz[2], brr[2], bh[2];
#pragma unroll
        for (int j = 0; j < 2; j++) {
            bz[j]  = br1[uu0 + j];
            brr[j] = br1[NU1 + uu0 + j];
            bh[j]  = br1[2*NU1 + uu0 + j];
        }
        const float* hrow = sH + lane*KP;

        for (int t = 0; t < TT; t++) {
            const float* hg = h1p + (t & 1) * (BB*NU1);
            float*       hn = h1p + ((t + 1) & 1) * (BB*NU1);
            const float* sXc = sX + (t & 1)*32*XS;

            for (int i = tid; i < 32*(NU1/4); i += NTHR) {
                int bb = i / (NU1/4), kk = i % (NU1/4);
                cp_async16(sH_s + (uint32_t)(bb*KP + kk*4)*4,
                           hg + (size_t)(b0+bb)*NU1 + kk*4);
            }
            cp_commit();
            cp_wait0();
            __syncthreads();

            if (w < 8) {
                unsigned long long az[2] = {}, ar[2] = {}, ah[2] = {};
#pragma unroll 4
                for (int k = 0; k < NU1; k += 4) {
                    ulonglong2 h2 = *reinterpret_cast<const ulonglong2*>(hrow + k);
#pragma unroll
                    for (int j = 0; j < 2; j++) {
                        const float* ub = sU + ((w*2 + j)*3)*KP + k;
                        ulonglong2 uz = *reinterpret_cast<const ulonglong2*>(ub);
                        ulonglong2 ur = *reinterpret_cast<const ulonglong2*>(ub + KP);
                        ulonglong2 uh = *reinterpret_cast<const ulonglong2*>(ub + 2*KP);
                        az[j] = fma2(h2.x, uz.x, az[j]); az[j] = fma2(h2.y, uz.y, az[j]);
                        ar[j] = fma2(h2.x, ur.x, ar[j]); ar[j] = fma2(h2.y, ur.y, ar[j]);
                        ah[j] = fma2(h2.x, uh.x, ah[j]); ah[j] = fma2(h2.y, uh.y, ah[j]);
                    }
                }
                const int mk = (sMask[lane*8 + (t >> 5)] >> (t & 31)) & 1;
                float hv[2];
#pragma unroll
                for (int j = 0; j < 2; j++) {
                    float vz = hsum2(az[j]), vr = hsum2(ar[j]), vh = hsum2(ah[j]);
                    int lu = w*2 + j;
                    float xz = sXc[lane*XS + lu];
                    float xr = sXc[lane*XS + UT + lu];
                    float xh = sXc[lane*XS + 2*UT + lu];
                    float z  = 1.f / (1.f + __expf(-(xz + vz + bz[j])));
                    float r  = 1.f / (1.f + __expf(-(xr + vr + brr[j])));
                    float hh = tanhf(xh + r * (vh + bh[j]));
                    float hold = hrow[uu0 + j];
                    float hnew = z*hold + (1.f - z)*hh;
                    hv[j] = mk ? hnew : hold;
                }
                *reinterpret_cast<float2*>(hn + (size_t)b*NU1 + uu0) = make_float2(hv[0], hv[1]);
                size_t ob = (((size_t)t*4 + grp)*NU1 + uu0)*32 + lane;
                o1g[ob]      = hv[0];
                o1g[ob + 32] = hv[1];
            }

            if (t + 1 < TT) {
                uint32_t dst = sX_s + (uint32_t)(((t+1) & 1)*32*XS)*4;
                for (int i = tid; i < 32*(XS/4); i += NTHR) {
                    int bb = i / (XS/4), q = i % (XS/4);
                    int g = q / (UT/4), l4 = q % (UT/4);
                    cp_async16(dst + (uint32_t)(bb*XS + g*UT + l4*4)*4,
                               xw1 + ((size_t)(t+1)*BB + b0 + bb)*(size_t)(3*NU1)
                                   + (size_t)g*NU1 + u0 + l4*4);
                }
                cp_commit();
            }

            __syncthreads();
            if (tid == 0) {
                unsigned target = (unsigned)(t + 1);
                unsigned arr = atom_arrive(g_cnt1 + grp*32);
                if (arr == 24u) {
                    st_relaxed(g_cnt1 + grp*32, 0);
                    st_release(g_gen1  + grp*32, target);
                    st_release(g_gen1c + grp*32, target);
                } else {
                    while (ld_acquire(g_gen1 + grp*32) < target) { }
                }
            }
            __syncthreads();
        }
    } else {
        // ---------------- L2 role: split-barrier pipelined ----------------
        constexpr int UT2 = 20, COLS = 3*UT2;
        constexpr int KW1 = NU1 + 4;
        float* sW2 = sm;                             // [60][404]
        float* sU2 = sW2 + COLS*KW1;                 // [60][204]
        float* sO1 = sU2 + COLS*NU2P;                // [400][32]  (bulk A dst)
        float* sH2 = sO1 + NU1*32;                   // [32][204]  (bulk B dst)
        unsigned* sMask = (unsigned*)(sH2 + 32*NU2P);// [32][8]
        uint32_t  mbarA = (uint32_t)__cvta_generic_to_shared(sMask + 32*8);
        uint32_t  mbarB = mbarA + 8;

        const int ci  = blockIdx.x - L1_CTAS;
        const int u20 = (ci % 10) * UT2;
        const int grp = ci / 10;
        const int b0  = grp * 32;
        const int b   = b0 + lane;

        for (int i = tid; i < COLS*NU1; i += NTHR) {
            int k = i / COLS, c = i % COLS;
            int ul = c / 3, g = c % 3;
            sW2[c*KW1 + k] = W2[(size_t)k*(3*NU2) + g*NU2 + u20 + ul];
        }
        for (int i = tid; i < COLS*NU2; i += NTHR) {
            int k = i / COLS, c = i % COLS;
            int ul = c / 3, g = c % 3;
            sU2[c*NU2P + k] = Ur2[(size_t)k*(3*NU2) + g*NU2 + u20 + ul];
        }
        for (int i = tid; i < 32*8; i += NTHR) {
            int bb = i >> 3, wd = i & 7;
            unsigned m = 0;
            for (int j = 0; j < 32; j++)
                m |= (tokens[(b0 + bb)*TT + wd*32 + j] != 0 ? 1u : 0u) << j;
            sMask[bb*8 + wd] = m;
        }

        float bi[6], brc[6];
#pragma unroll
        for (int j = 0; j < 6; j++) {
            int c = w*6 + j;
            int ul = c / 3, g = c % 3;
            bi[j]  = b2full[g*NU2 + u20 + ul];
            brc[j] = b2full[3*NU2 + g*NU2 + u20 + ul];
        }

        const uint32_t sO1_s = (uint32_t)__cvta_generic_to_shared(sO1);
        const uint32_t sH2_s = (uint32_t)__cvta_generic_to_shared(sH2);
        const float* h2row = sH2 + lane*NU2P;

        if (tid == 0) { mbar_init(mbarA); mbar_init(mbarB); }
        __syncthreads();

        for (int t = 0; t < TT; t++) {
            const float* hg = h2p + (t & 1) * (BB*NU2P);
            float*       hn = h2p + ((t + 1) & 1) * (BB*NU2P);

            // 1) producer flag -> bulk o1(t)
            if (tid == 0) {
                unsigned need = (unsigned)(t + 1);
                while (ld_acquire(g_gen1c + grp*32) < need) { }
                mbar_expect_tx(mbarA, (uint32_t)(NU1*32*4));
                bulk_g2s(sO1_s, o1g + ((size_t)t*4 + grp)*NU1*32, NU1*32*4, mbarA);
            }
            mbar_wait(mbarA, (uint32_t)(t & 1));

            // 2) projection (needs only o1) — overlaps peers' h2 completion
            unsigned long long accP[6] = {}, accR[6] = {};
#pragma unroll 2
            for (int k = 0; k < NU1; k += 4) {
                float o0 = sO1[(k+0)*32 + lane];
                float o1 = sO1[(k+1)*32 + lane];
                float o2 = sO1[(k+2)*32 + lane];
                float o3 = sO1[(k+3)*32 + lane];
                unsigned long long p01 = pack2(o0, o1), p23 = pack2(o2, o3);
#pragma unroll
                for (int j = 0; j < 6; j++) {
                    const float* wp = sW2 + (w*6 + j)*KW1 + k;
                    ulonglong2 wv = *reinterpret_cast<const ulonglong2*>(wp);
                    accP[j] = fma2(p01, wv.x, accP[j]);
                    accP[j] = fma2(p23, wv.y, accP[j]);
                }
            }

            // 3) own-group h2(t) ready? (split barrier wait) -> bulk h2(t)
            if (tid == 0) {
                while (ld_acquire(g_gen2 + grp*32) < (unsigned)t) { }
                mbar_expect_tx(mbarB, (uint32_t)(32*NU2P*4));
                bulk_g2s(sH2_s, hg + (size_t)b0*NU2P, 32*NU2P*4, mbarB);
            }
            mbar_wait(mbarB, (uint32_t)(t & 1));

            // 4) recurrence
#pragma unroll 2
            for (int k = 0; k < NU2; k += 4) {
                ulonglong2 h2v = *reinterpret_cast<const ulonglong2*>(h2row + k);
#pragma unroll
                for (int j = 0; j < 6; j++) {
                    const float* up = sU2 + (w*6 + j)*NU2P + k;
                    ulonglong2 uv = *reinterpret_cast<const ulonglong2*>(up);
                    accR[j] = fma2(h2v.x, uv.x, accR[j]);
                    accR[j] = fma2(h2v.y, uv.y, accR[j]);
                }
            }

            const int mk = (sMask[lane*8 + (t >> 5)] >> (t & 31)) & 1;
#pragma unroll
            for (int je = 0; je < 2; je++) {
                int ug = u20 + 2*w + je;
                float Pz = hsum2(accP[je*3+0]) + bi[je*3+0];
                float Pr = hsum2(accP[je*3+1]) + bi[je*3+1];
                float Ph = hsum2(accP[je*3+2]) + bi[je*3+2];
                float Rz = hsum2(accR[je*3+0]) + brc[je*3+0];
                float Rr = hsum2(accR[je*3+1]) + brc[je*3+1];
                float Rh = hsum2(accR[je*3+2]) + brc[je*3+2];
                float z  = 1.f / (1.f + __expf(-(Pz + Rz)));
                float r  = 1.f / (1.f + __expf(-(Pr + Rr)));
                float hh = tanhf(Ph + r * Rh);
                float hold = h2row[ug];
                float hnew = z*hold + (1.f - z)*hh;
                float hv = mk ? hnew : hold;
                hn[(size_t)b*NU2P + ug] = hv;
                o2t[((size_t)t*NU2 + ug)*BB + b] = hv;
            }

            // 5) all reads of sO1/sH2 done; arrive (release-only, NO wait)
            __syncthreads();
            if (tid == 0) {
                unsigned arr = atom_arrive(g_cnt2 + grp*32);
                if (arr == 9u) {
                    st_relaxed(g_cnt2 + grp*32, 0);
                    st_release(g_gen2 + grp*32, (unsigned)(t + 1));
                }
            }
        }
    }
}

extern "C" void kernel_launch(void* const* d_in, const int* in_sizes, int n_in,
                              void* d_out, int out_size)
{
    const int*   tokens = (const int*)  d_in[0];
    const float* emb    = (const float*)d_in[1];
    const float* gamma  = (const float*)d_in[2];
    const float* beta   = (const float*)d_in[3];
    const float* mmean  = (const float*)d_in[4];
    const float* mvar   = (const float*)d_in[5];
    const float* W1     = (const float*)d_in[6];
    const float* Ur1    = (const float*)d_in[7];
    const float* b1     = (const float*)d_in[8];
    const float* W2     = (const float*)d_in[9];
    const float* Ur2    = (const float*)d_in[10];
    const float* b2     = (const float*)d_in[11];

    float* out  = (float*)d_out;
    float* out2 = out + OUT2_OFF;
    float* out1 = out + OUT1_OFF;
    float* h2o  = out + H2_OFF;
    float* h1o  = out + H1_OFF;

    void *p_xn, *p_xw1, *p_o1g, *p_o2t, *p_h1, *p_h2;
    cudaGetSymbolAddress(&p_xn,  g_xn);
    cudaGetSymbolAddress(&p_xw1, g_xw1);
    cudaGetSymbolAddress(&p_o1g, g_o1g);
    cudaGetSymbolAddress(&p_o2t, g_o2t);
    cudaGetSymbolAddress(&p_h1,  g_h1);
    cudaGetSymbolAddress(&p_h2,  g_h2);
    float* xn  = (float*)p_xn;
    float* xw1 = (float*)p_xw1;
    float* o1g = (float*)p_o1g;
    float* o2t = (float*)p_o2t;
    float* h1p = (float*)p_h1;
    float* h2p = (float*)p_h2;

    cudaFuncSetAttribute(fused_gru, cudaFuncAttributeMaxDynamicSharedMemorySize, FUSED_SMEM);

    embed_bn<<<(BB*TT*EMBD + 255)/256, 256>>>(tokens, emb, gamma, beta, mmean, mvar);
    init_state<<<(2*BB*NU1 + 255)/256, 256>>>();

    // xw1 = xn @ W1 + b1[0]
    sgemm128<<<dim3((3*NU1 + 127)/128, (BB*TT)/128), 256>>>(xn, W1, b1, xw1, 3*NU1, EMBD);

    // fused persistent L1+L2
    fused_gru<<<140, NTHR, FUSED_SMEM>>>(xw1, Ur1, b1 + 3*NU1, W2, Ur2, b2,
                                         tokens, o1g, o2t, h1p, h2p);

    copy_h<<<(BB*NU1 + 255)/256, 256>>>(h1p, h1o, BB*NU1);                 // T even -> buf 0
    copy_h_strided<<<(BB*NU2 + 255)/256, 256>>>(h2p, h2o, NU2, NU2P);
    transpose_o1<<<dim3(TT, 25, 4), dim3(32, 8)>>>(o1g, out1);
    transpose_tub<<<dim3(TT, (NU2 + 31)/32, BB/32), dim3(32, 8)>>>(o2t, out2, NU2);
}